// round 3
// baseline (speedup 1.0000x reference)
#include <cuda_runtime.h>
#include <stdint.h>

// MultiEchoNeighborBlock: per-pixel 7x7 KNN (k=9) over point distances,
// gather range values in exact rank order, 20->32 linear + leaky relu.
//
// Shapes: x (4, 8, 64, 2048) f32   [ch0,ch1 = ranges; ch2-4 = pts echo0; ch5-7 = pts echo1]
//         range_weight (1, 32, 20) f32
//         out (4, 32, 64, 2048) f32

#define HH 64
#define WW 2048
#define HWP (HH * WW)
#define NCH 8
#define BX 128        // pixels along W per block
#define BY 2          // rows per block
#define TPB (BX * BY)
#define TW (BX + 6)   // tile width  (halo 3 each side)
#define TH (BY + 6)   // tile height

// Branchless stable insert of unique 64-bit key into ascending sorted a[0..8].
// Keys are unique ((dist_bits<<32)|smem_offset), so strict '<' compare-swap
// chain yields the exact reference order (ascending dist, ties by lower index).
__device__ __forceinline__ void ins9(unsigned long long k, unsigned long long (&a)[9]) {
#pragma unroll
    for (int j = 0; j < 9; ++j) {
        bool lt = k < a[j];
        unsigned long long mn = lt ? k : a[j];
        unsigned long long mx = lt ? a[j] : k;
        a[j] = mn;
        k = mx;
    }
}

__global__ __launch_bounds__(TPB)
void knn_block_kernel(const float* __restrict__ x,
                      const float* __restrict__ rw,
                      float* __restrict__ out) {
    __shared__ float4 tile[TH][TW];   // (px, py, pz, range_ch0)
    __shared__ float wt[20][32];      // transposed weights: wt[c][k]

    const int tid = threadIdx.x;
    const int b = blockIdx.z;
    const int h0 = blockIdx.y * BY;
    const int w0 = blockIdx.x * BX;
    const float* X = x + (size_t)b * NCH * HWP;

    // Load + transpose weights (W[k,c] row-major -> wt[c][k]).
    for (int i = tid; i < 640; i += TPB) {
        wt[i % 20][i / 20] = rw[i];
    }
    // Load tile: channels 2,3,4 (points) + channel 0 (range), zero-padded.
    for (int i = tid; i < TH * TW; i += TPB) {
        int r = i / TW, c = i % TW;
        int gh = h0 - 3 + r, gw = w0 - 3 + c;
        float4 v = make_float4(0.f, 0.f, 0.f, 0.f);
        if (gh >= 0 && gh < HH && gw >= 0 && gw < WW) {
            int o = gh * WW + gw;
            v.x = X[2 * HWP + o];
            v.y = X[3 * HWP + o];
            v.z = X[4 * HWP + o];
            v.w = X[0 * HWP + o];
        }
        tile[r][c] = v;
    }
    __syncthreads();

    const int tx = tid % BX;
    const int ty = tid / BX;
    const int h = h0 + ty;
    const int w = w0 + tx;
    const int pix = h * WW + w;

    const float4 c4 = tile[ty + 3][tx + 3];
    const float q0x = c4.x, q0y = c4.y, q0z = c4.z;
    const float q1x = X[5 * HWP + pix];
    const float q1y = X[6 * HWP + pix];
    const float q1z = X[7 * HWP + pix];
    const float r1c = X[1 * HWP + pix];

    unsigned long long a0[9], a1[9];
#pragma unroll
    for (int j = 0; j < 9; ++j) { a0[j] = ~0ull; a1[j] = ~0ull; }

    const char* tb = (const char*)tile;
    const unsigned base = (unsigned)((ty * TW + tx) * 16);

#pragma unroll 1
    for (int dy = 0; dy < 7; ++dy) {
        unsigned roff = base + (unsigned)dy * (TW * 16u);
#pragma unroll
        for (int dx = 0; dx < 7; ++dx) {
            unsigned off = roff + (unsigned)(dx * 16);
            float4 p = *(const float4*)(tb + off);

            // Echo 0 distance: no FMA contraction (match XLA mul/add rounding),
            // IEEE sqrt (match jnp.sqrt) so tie pattern is bit-identical.
            float d0x = __fadd_rn(q0x, -p.x);
            float d0y = __fadd_rn(q0y, -p.y);
            float d0z = __fadd_rn(q0z, -p.z);
            float s0 = __fadd_rn(__fadd_rn(__fmul_rn(d0x, d0x), __fmul_rn(d0y, d0y)),
                                 __fmul_rn(d0z, d0z));
            float dist0 = __fsqrt_rn(s0);
            unsigned long long k0 =
                ((unsigned long long)__float_as_uint(dist0) << 32) | (unsigned long long)off;
            ins9(k0, a0);

            // Echo 1
            float d1x = __fadd_rn(q1x, -p.x);
            float d1y = __fadd_rn(q1y, -p.y);
            float d1z = __fadd_rn(q1z, -p.z);
            float s1 = __fadd_rn(__fadd_rn(__fmul_rn(d1x, d1x), __fmul_rn(d1y, d1y)),
                                 __fmul_rn(d1z, d1z));
            float dist1 = __fsqrt_rn(s1);
            unsigned long long k1 =
                ((unsigned long long)__float_as_uint(dist1) << 32) | (unsigned long long)off;
            ins9(k1, a1);
        }
    }

    // Gather range values in rank order (low word of key == smem offset of float4;
    // +12 bytes = the .w / range component).
    float feats[20];
#pragma unroll
    for (int s = 0; s < 9; ++s) {
        feats[s]      = *(const float*)(tb + (unsigned)a0[s] + 12u);
        feats[10 + s] = *(const float*)(tb + (unsigned)a1[s] + 12u);
    }
    feats[9]  = c4.w;  // center range ch0
    feats[19] = r1c;   // center range ch1

    // 20 -> 32 linear
    float acc[32];
#pragma unroll
    for (int k = 0; k < 32; ++k) acc[k] = 0.f;
#pragma unroll
    for (int c = 0; c < 20; ++c) {
        float f = feats[c];
        const float4* wp = (const float4*)&wt[c][0];
#pragma unroll
        for (int k4 = 0; k4 < 8; ++k4) {
            float4 wv = wp[k4];
            acc[k4 * 4 + 0] += f * wv.x;
            acc[k4 * 4 + 1] += f * wv.y;
            acc[k4 * 4 + 2] += f * wv.z;
            acc[k4 * 4 + 3] += f * wv.w;
        }
    }

    float* O = out + (size_t)b * 32 * HWP + pix;
#pragma unroll
    for (int k = 0; k < 32; ++k) {
        float v = acc[k];
        v = (v >= 0.f) ? v : 0.01f * v;   // leaky_relu(0.01)
        O[(size_t)k * HWP] = v;
    }
}

extern "C" void kernel_launch(void* const* d_in, const int* in_sizes, int n_in,
                              void* d_out, int out_size) {
    const float* x  = (const float*)d_in[0];
    const float* rw = (const float*)d_in[1];
    // Defensive: identify the 640-element weight tensor by size.
    if (n_in >= 2 && in_sizes[0] == 640) {
        const float* t = x; x = rw; rw = t;
    }
    dim3 grid(WW / BX, HH / BY, 4);
    knn_block_kernel<<<grid, TPB>>>(x, rw, (float*)d_out);
}

// round 5
// speedup vs baseline: 1.5232x; 1.5232x over previous
#include <cuda_runtime.h>
#include <stdint.h>

// MultiEchoNeighborBlock: per-pixel 7x7 KNN (k=9) over point distances,
// gather range values in exact rank order, 20->32 linear + leaky relu.
//
// Shapes: x (4, 8, 64, 2048) f32   [ch0,ch1 = ranges; ch2-4 = pts echo0; ch5-7 = pts echo1]
//         range_weight (1, 32, 20) f32
//         out (4, 32, 64, 2048) f32
//
// R5: sticky-predicate stable insert. R4's CAS chain compared the CARRIED
// element against residents, which swapped equal-keyed residents during
// displacement (rare sqrt-rounding ties -> rel_err 1.3e-3). Here every
// comparison is (original incoming key < resident), OR-accumulated into a
// sticky predicate; after the trigger point the chain is a pure shift-down.
// Ties: incoming (later patch index) never displaces an equal resident, and
// residents are never re-compared -> exact top_k stable order, always.
// Per stage: 1 FSETP.LT.OR (fma pipe) + 4 SEL (alu) vs R3's 6 alu.

#define HH 64
#define WW 2048
#define HWP (HH * WW)
#define NCH 8
#define BX 128        // pixels along W per block
#define BY 2          // rows per block
#define TPB (BX * BY)
#define TW (BX + 6)   // tile width  (halo 3 each side)
#define TH (BY + 6)   // tile height

__device__ __forceinline__ void ins9s(float kin, float vin,
                                      float (&ak)[9], float (&av)[9]) {
    bool p = false;
    float ck = kin, cv = vin;
#pragma unroll
    for (int j = 0; j < 9; ++j) {
        p = p | (kin < ak[j]);     // sticky: compare ORIGINAL key only
        float tk = ak[j], tv = av[j];
        ak[j] = p ? ck : tk;
        av[j] = p ? cv : tv;
        ck = p ? tk : ck;          // after trigger: carry the shifted resident
        cv = p ? tv : cv;
    }
}

__global__ __launch_bounds__(TPB)
void knn_block_kernel(const float* __restrict__ x,
                      const float* __restrict__ rw,
                      float* __restrict__ out) {
    __shared__ float4 tile[TH][TW];   // (px, py, pz, range_ch0)
    __shared__ float wt[20][32];      // transposed weights: wt[c][k]

    const int tid = threadIdx.x;
    const int b = blockIdx.z;
    const int h0 = blockIdx.y * BY;
    const int w0 = blockIdx.x * BX;
    const float* X = x + (size_t)b * NCH * HWP;

    // Load + transpose weights (W[k,c] row-major -> wt[c][k]).
    for (int i = tid; i < 640; i += TPB) {
        wt[i % 20][i / 20] = rw[i];
    }
    // Load tile: channels 2,3,4 (points) + channel 0 (range), zero-padded.
    for (int i = tid; i < TH * TW; i += TPB) {
        int r = i / TW, c = i % TW;
        int gh = h0 - 3 + r, gw = w0 - 3 + c;
        float4 v = make_float4(0.f, 0.f, 0.f, 0.f);
        if (gh >= 0 && gh < HH && gw >= 0 && gw < WW) {
            int o = gh * WW + gw;
            v.x = X[2 * HWP + o];
            v.y = X[3 * HWP + o];
            v.z = X[4 * HWP + o];
            v.w = X[0 * HWP + o];
        }
        tile[r][c] = v;
    }
    __syncthreads();

    const int tx = tid % BX;
    const int ty = tid / BX;
    const int h = h0 + ty;
    const int w = w0 + tx;
    const int pix = h * WW + w;

    const float4 c4 = tile[ty + 3][tx + 3];
    const float q0x = c4.x, q0y = c4.y, q0z = c4.z;
    const float q1x = X[5 * HWP + pix];
    const float q1y = X[6 * HWP + pix];
    const float q1z = X[7 * HWP + pix];
    const float r1c = X[1 * HWP + pix];

    const float INF = __int_as_float(0x7f800000);
    float ak0[9], av0[9], ak1[9], av1[9];
#pragma unroll
    for (int j = 0; j < 9; ++j) {
        ak0[j] = INF; av0[j] = 0.f;
        ak1[j] = INF; av1[j] = 0.f;
    }

#pragma unroll 1
    for (int dy = 0; dy < 7; ++dy) {
        const float4* row = &tile[ty + dy][tx];
#pragma unroll
        for (int dx = 0; dx < 7; ++dx) {
            float4 p = row[dx];

            // Echo 0 distance: no FMA contraction (match XLA mul/add rounding),
            // IEEE sqrt (match jnp.sqrt) so ordering is bit-identical.
            float d0x = __fadd_rn(q0x, -p.x);
            float d0y = __fadd_rn(q0y, -p.y);
            float d0z = __fadd_rn(q0z, -p.z);
            float s0 = __fadd_rn(__fadd_rn(__fmul_rn(d0x, d0x), __fmul_rn(d0y, d0y)),
                                 __fmul_rn(d0z, d0z));
            float dist0 = __fsqrt_rn(s0);
            ins9s(dist0, p.w, ak0, av0);

            // Echo 1
            float d1x = __fadd_rn(q1x, -p.x);
            float d1y = __fadd_rn(q1y, -p.y);
            float d1z = __fadd_rn(q1z, -p.z);
            float s1 = __fadd_rn(__fadd_rn(__fmul_rn(d1x, d1x), __fmul_rn(d1y, d1y)),
                                 __fmul_rn(d1z, d1z));
            float dist1 = __fsqrt_rn(s1);
            ins9s(dist1, p.w, ak1, av1);
        }
    }

    // Features: payloads already sorted in rank order — no gather needed.
    float feats[20];
#pragma unroll
    for (int s = 0; s < 9; ++s) {
        feats[s]      = av0[s];
        feats[10 + s] = av1[s];
    }
    feats[9]  = c4.w;  // center range ch0
    feats[19] = r1c;   // center range ch1

    // 20 -> 32 linear
    float acc[32];
#pragma unroll
    for (int k = 0; k < 32; ++k) acc[k] = 0.f;
#pragma unroll
    for (int c = 0; c < 20; ++c) {
        float f = feats[c];
        const float4* wp = (const float4*)&wt[c][0];
#pragma unroll
        for (int k4 = 0; k4 < 8; ++k4) {
            float4 wv = wp[k4];
            acc[k4 * 4 + 0] += f * wv.x;
            acc[k4 * 4 + 1] += f * wv.y;
            acc[k4 * 4 + 2] += f * wv.z;
            acc[k4 * 4 + 3] += f * wv.w;
        }
    }

    float* O = out + (size_t)b * 32 * HWP + pix;
#pragma unroll
    for (int k = 0; k < 32; ++k) {
        float v = acc[k];
        v = (v >= 0.f) ? v : 0.01f * v;   // leaky_relu(0.01)
        O[(size_t)k * HWP] = v;
    }
}

extern "C" void kernel_launch(void* const* d_in, const int* in_sizes, int n_in,
                              void* d_out, int out_size) {
    const float* x  = (const float*)d_in[0];
    const float* rw = (const float*)d_in[1];
    // Defensive: identify the 640-element weight tensor by size.
    if (n_in >= 2 && in_sizes[0] == 640) {
        const float* t = x; x = rw; rw = t;
    }
    dim3 grid(WW / BX, HH / BY, 4);
    knn_block_kernel<<<grid, TPB>>>(x, rw, (float*)d_out);
}